// round 15
// baseline (speedup 1.0000x reference)
#include <cuda_runtime.h>
#include <cuda_bf16.h>
#include <cuda_fp16.h>
#include <cstdint>
#include <cstddef>

#define NN   100000
#define MAXE 1600000
#define NB   391          // ceil(NN/256)

// ---------------- device scratch ----------------
__device__ int   g_degi[NN];       // zero at process start; re-zeroed by k_agg1
__device__ float g_dinv[NN];
__device__ int   g_rowptr[NN + 1];
__device__ int   g_bsum[NB];
__device__ int   g_epos[MAXE];     // within-bucket rank of each edge
__device__ int   g_csrc[MAXE];
__device__ uint8_t g_h1[(size_t)NN * 128];  // fp8: 16*dinv*(x@W1)
__device__ uint8_t g_t1[(size_t)NN * 128];  // fp8: 16*relu(agg1+b1)
__device__ uint8_t g_h2[(size_t)NN * 64];   // fp8: 16*dinv*(t1@W2)
__device__ float g_acc[64];
__device__ unsigned int g_done;

// ---------------- inline edge dtype detection (per block) -----------------
__device__ __forceinline__ int detect_e64(const void* eidx, int* sh) {
    if (threadIdx.x < 32) {
        unsigned long long v = ((const unsigned long long*)eidx)[threadIdx.x];
        unsigned m = __ballot_sync(0xffffffffu, (v >> 32) != 0ULL);
        if (threadIdx.x == 0) *sh = (m == 0u);
    }
    __syncthreads();
    return *sh;
}

// ---------------- degree count (4 edges/thread, records bucket rank) ------
__global__ void k_degcount(const void* __restrict__ eidx, long long E) {
    __shared__ int sh;
    int e64 = detect_e64(eidx, &sh);
    long long base = (blockIdx.x * (long long)blockDim.x + threadIdx.x) * 4;
    if (base >= E) return;
    bool fast = (base + 3 < E) && ((E & 3LL) == 0);
    if (e64) {
        const long long* p = (const long long*)eidx + E;   // dst half
        if (fast) {
            longlong4 d4 = *(const longlong4*)(p + base);
            int4 r;
            r.x = atomicAdd(&g_degi[(int)d4.x], 1);
            r.y = atomicAdd(&g_degi[(int)d4.y], 1);
            r.z = atomicAdd(&g_degi[(int)d4.z], 1);
            r.w = atomicAdd(&g_degi[(int)d4.w], 1);
            *(int4*)&g_epos[base] = r;
        } else {
            for (int k = 0; k < 4 && base + k < E; k++)
                g_epos[base + k] = atomicAdd(&g_degi[(int)p[base + k]], 1);
        }
    } else {
        const int* p = (const int*)eidx + E;
        if (fast) {
            int4 d4 = *(const int4*)(p + base);
            int4 r;
            r.x = atomicAdd(&g_degi[d4.x], 1);
            r.y = atomicAdd(&g_degi[d4.y], 1);
            r.z = atomicAdd(&g_degi[d4.z], 1);
            r.w = atomicAdd(&g_degi[d4.w], 1);
            *(int4*)&g_epos[base] = r;
        } else {
            for (int k = 0; k < 4 && base + k < E; k++)
                g_epos[base + k] = atomicAdd(&g_degi[p[base + k]], 1);
        }
    }
}

// ---------------- scan stage 1: per-tile totals (+ dinv) ------------------
__global__ void k_scan1() {
    __shared__ int sm[256];
    int i = blockIdx.x * 256 + threadIdx.x;
    int v = (i < NN) ? g_degi[i] : 0;
    if (i < NN) g_dinv[i] = rsqrtf((float)(v + 1));   // +1 self loop
    sm[threadIdx.x] = v;
    __syncthreads();
    for (int o = 128; o > 0; o >>= 1) {
        if (threadIdx.x < o) sm[threadIdx.x] += sm[threadIdx.x + o];
        __syncthreads();
    }
    if (threadIdx.x == 0) g_bsum[blockIdx.x] = sm[0];
}

// ---------------- scan stage 2+3 merged: rowptr (+ zero acc/done) ---------
__global__ void k_scan23() {
    __shared__ int red[256];
    __shared__ int sm[256];
    int bid = blockIdx.x;

    int partial = 0;
    for (int j = threadIdx.x; j < bid; j += 256) partial += g_bsum[j];
    red[threadIdx.x] = partial;
    __syncthreads();
    for (int o = 128; o > 0; o >>= 1) {
        if (threadIdx.x < o) red[threadIdx.x] += red[threadIdx.x + o];
        __syncthreads();
    }
    int boff = red[0];

    int i = bid * 256 + threadIdx.x;
    int v = (i < NN) ? g_degi[i] : 0;
    sm[threadIdx.x] = v;
    __syncthreads();
    for (int o = 1; o < 256; o <<= 1) {
        int t = (threadIdx.x >= o) ? sm[threadIdx.x - o] : 0;
        __syncthreads();
        sm[threadIdx.x] += t;
        __syncthreads();
    }
    int excl = boff + sm[threadIdx.x] - v;
    if (i < NN) g_rowptr[i] = excl;
    if (i == NN - 1) g_rowptr[NN] = excl + v;

    if (bid == 0) {
        if (threadIdx.x < 64) g_acc[threadIdx.x] = 0.f;
        if (threadIdx.x == 64) g_done = 0u;
    }
}

// ---------------- scatter: atomic-free, 4 edges/thread --------------------
__global__ void k_scatter(const void* __restrict__ eidx, long long E) {
    __shared__ int sh;
    int e64 = detect_e64(eidx, &sh);
    long long base = (blockIdx.x * (long long)blockDim.x + threadIdx.x) * 4;
    if (base >= E) return;
    bool fast = (base + 3 < E) && ((E & 3LL) == 0);
    if (e64) {
        const long long* ps = (const long long*)eidx;
        const long long* pd = ps + E;
        if (fast) {
            longlong4 s4 = *(const longlong4*)(ps + base);
            longlong4 d4 = *(const longlong4*)(pd + base);
            int4 ep = *(const int4*)&g_epos[base];
            g_csrc[g_rowptr[(int)d4.x] + ep.x] = (int)s4.x;
            g_csrc[g_rowptr[(int)d4.y] + ep.y] = (int)s4.y;
            g_csrc[g_rowptr[(int)d4.z] + ep.z] = (int)s4.z;
            g_csrc[g_rowptr[(int)d4.w] + ep.w] = (int)s4.w;
        } else {
            for (int k = 0; k < 4 && base + k < E; k++)
                g_csrc[g_rowptr[(int)pd[base + k]] + g_epos[base + k]] =
                    (int)ps[base + k];
        }
    } else {
        const int* ps = (const int*)eidx;
        const int* pd = ps + E;
        if (fast) {
            int4 s4 = *(const int4*)(ps + base);
            int4 d4 = *(const int4*)(pd + base);
            int4 ep = *(const int4*)&g_epos[base];
            g_csrc[g_rowptr[d4.x] + ep.x] = s4.x;
            g_csrc[g_rowptr[d4.y] + ep.y] = s4.y;
            g_csrc[g_rowptr[d4.z] + ep.z] = s4.z;
            g_csrc[g_rowptr[d4.w] + ep.w] = s4.w;
        } else {
            for (int k = 0; k < 4 && base + k < E; k++)
                g_csrc[g_rowptr[pd[base + k]] + g_epos[base + k]] = ps[base + k];
        }
    }
}

// ---------------- fp8 helpers ----------------
__device__ __forceinline__ uint16_t pack_e4m3_2(float lo, float hi) {
    uint16_t r;
    asm("cvt.rn.satfinite.e4m3x2.f32 %0, %1, %2;" : "=h"(r) : "f"(hi), "f"(lo));
    return r;
}
// u32 of 4 e4m3 -> two f16x2 registers (no fp32 conversion)
__device__ __forceinline__ void e4m3x4_to_h2(uint32_t v, uint32_t& h01, uint32_t& h23) {
    asm("cvt.rn.f16x2.e4m3x2 %0, %1;" : "=r"(h01)
        : "h"((unsigned short)(v & 0xffffu)));
    asm("cvt.rn.f16x2.e4m3x2 %0, %1;" : "=r"(h23)
        : "h"((unsigned short)(v >> 16)));
}
__device__ __forceinline__ void unpack_e4m3_4(uint32_t v, float* f) {
    uint32_t h01, h23;
    e4m3x4_to_h2(v, h01, h23);
    float2 fa = __half22float2(*reinterpret_cast<__half2*>(&h01));
    float2 fb = __half22float2(*reinterpret_cast<__half2*>(&h23));
    f[0] = fa.x; f[1] = fa.y; f[2] = fb.x; f[3] = fb.y;
}
__device__ __forceinline__ uint2 fp8x4_to_bf16x4(uint32_t v) {
    float f[4];
    unpack_e4m3_4(v, f);
    __nv_bfloat162 lo = __float22bfloat162_rn(make_float2(f[0], f[1]));
    __nv_bfloat162 hi = __float22bfloat162_rn(make_float2(f[2], f[3]));
    return make_uint2(*(uint32_t*)&lo, *(uint32_t*)&hi);
}

// ---------------- tensor-core GEMM primitives ----------------
__device__ __forceinline__ uint32_t smem_u32(const void* p) {
    return (uint32_t)__cvta_generic_to_shared(p);
}
__device__ __forceinline__ void ldsm4(uint32_t* r, uint32_t addr) {
    asm volatile("ldmatrix.sync.aligned.m8n8.x4.shared.b16 {%0,%1,%2,%3},[%4];"
                 : "=r"(r[0]), "=r"(r[1]), "=r"(r[2]), "=r"(r[3]) : "r"(addr));
}
__device__ __forceinline__ void ldsm4t(uint32_t* r, uint32_t addr) {
    asm volatile("ldmatrix.sync.aligned.m8n8.x4.trans.shared.b16 {%0,%1,%2,%3},[%4];"
                 : "=r"(r[0]), "=r"(r[1]), "=r"(r[2]), "=r"(r[3]) : "r"(addr));
}
__device__ __forceinline__ void mma16816(float* d, const uint32_t* a, const uint32_t* b) {
    asm volatile(
        "mma.sync.aligned.m16n8k16.row.col.f32.bf16.bf16.f32 "
        "{%0,%1,%2,%3},{%4,%5,%6,%7},{%8,%9},{%0,%1,%2,%3};"
        : "+f"(d[0]), "+f"(d[1]), "+f"(d[2]), "+f"(d[3])
        : "r"(a[0]), "r"(a[1]), "r"(a[2]), "r"(a[3]), "r"(b[0]), "r"(b[1]));
}

// C[nrows,BN](fp8) = osc * rowscale[r] * (A[nrows,128] @ W[128,BN]).
// AMODE: 0 = A is fp32, 2 = A is fp8 (unpacked exactly to bf16).
template <int BN, int AMODE>
__global__ void __launch_bounds__(256)
k_gemm_tc(const void* __restrict__ Av, const float* __restrict__ W,
          const float* __restrict__ rowscale, float osc,
          uint8_t* __restrict__ C, int nrows) {
    const int LDA = 136;
    const int LDB = BN + 8;
    extern __shared__ __nv_bfloat16 smem[];
    __nv_bfloat16* As = smem;
    __nv_bfloat16* Bs = smem + 128 * LDA;

    int tid  = threadIdx.x;
    int lane = tid & 31;
    int w    = tid >> 5;
    int wm   = w & 3;
    int wn   = w >> 2;
    int row0 = blockIdx.x * 128;

    if (AMODE == 2) {
        const uint8_t* A = (const uint8_t*)Av;
        for (int idx = tid; idx < 128 * 16; idx += 256) {
            int r = idx >> 4, c8 = (idx & 15) * 8;
            uint2 v = make_uint2(0u, 0u);
            if (row0 + r < nrows)
                v = *(const uint2*)(A + (size_t)(row0 + r) * 128 + c8);
            uint2 lo = fp8x4_to_bf16x4(v.x);
            uint2 hi = fp8x4_to_bf16x4(v.y);
            *(uint4*)&As[r * LDA + c8] = make_uint4(lo.x, lo.y, hi.x, hi.y);
        }
    } else {
        const float* A = (const float*)Av;
        for (int idx = tid; idx < 128 * 32; idx += 256) {
            int r = idx >> 5, c4 = (idx & 31) * 4;
            float4 v = make_float4(0.f, 0.f, 0.f, 0.f);
            if (row0 + r < nrows)
                v = *(const float4*)(A + (size_t)(row0 + r) * 128 + c4);
            __nv_bfloat162 lo = __float22bfloat162_rn(make_float2(v.x, v.y));
            __nv_bfloat162 hi = __float22bfloat162_rn(make_float2(v.z, v.w));
            uint2 pk;
            pk.x = *(uint32_t*)&lo;
            pk.y = *(uint32_t*)&hi;
            *(uint2*)&As[r * LDA + c4] = pk;
        }
    }
    for (int idx = tid; idx < 128 * (BN / 4); idx += 256) {
        int r = idx / (BN / 4), c4 = (idx % (BN / 4)) * 4;
        float4 v = *(const float4*)(W + (size_t)r * BN + c4);
        __nv_bfloat162 lo = __float22bfloat162_rn(make_float2(v.x, v.y));
        __nv_bfloat162 hi = __float22bfloat162_rn(make_float2(v.z, v.w));
        uint2 pk;
        pk.x = *(uint32_t*)&lo;
        pk.y = *(uint32_t*)&hi;
        *(uint2*)&Bs[r * LDB + c4] = pk;
    }
    __syncthreads();

    const int NF8 = BN / 16;
    const int NT  = NF8 / 2;
    float acc[2][NF8][4];
#pragma unroll
    for (int i = 0; i < 2; i++)
#pragma unroll
        for (int j = 0; j < NF8; j++)
#pragma unroll
            for (int q = 0; q < 4; q++) acc[i][j][q] = 0.f;

    int rsel = lane & 15;
    int csel = (lane >> 4) * 8;
    int mw0  = wm * 32;
    int nw0  = wn * (BN / 2);

#pragma unroll
    for (int ks = 0; ks < 8; ks++) {
        int k0 = ks * 16;
        uint32_t af[2][4];
#pragma unroll
        for (int mi = 0; mi < 2; mi++)
            ldsm4(af[mi], smem_u32(&As[(mw0 + mi * 16 + rsel) * LDA + k0 + csel]));
        uint32_t bf[NT][4];
#pragma unroll
        for (int nt = 0; nt < NT; nt++)
            ldsm4t(bf[nt], smem_u32(&Bs[(k0 + rsel) * LDB + nw0 + nt * 16 + csel]));
#pragma unroll
        for (int mi = 0; mi < 2; mi++)
#pragma unroll
            for (int nj = 0; nj < NF8; nj++)
                mma16816(acc[mi][nj], af[mi], &bf[nj >> 1][(nj & 1) * 2]);
    }

    int g = lane >> 2, q = lane & 3;
#pragma unroll
    for (int mi = 0; mi < 2; mi++) {
        int r0 = row0 + mw0 + mi * 16 + g;
        float sc0 = (r0 < nrows)     ? rowscale[r0] * osc     : 0.f;
        float sc1 = (r0 + 8 < nrows) ? rowscale[r0 + 8] * osc : 0.f;
#pragma unroll
        for (int nj = 0; nj < NF8; nj++) {
            int col = nw0 + nj * 8 + q * 2;
            if (r0 < nrows)
                *(uint16_t*)(C + (size_t)r0 * BN + col) =
                    pack_e4m3_2(acc[mi][nj][0] * sc0, acc[mi][nj][1] * sc0);
            if (r0 + 8 < nrows)
                *(uint16_t*)(C + (size_t)(r0 + 8) * BN + col) =
                    pack_e4m3_2(acc[mi][nj][2] * sc1, acc[mi][nj][3] * sc1);
        }
    }
}

// ------- CSR fp8 gather-sum: 8-edge unroll, half2 tree, fp32 outer --------
template <int FB>
__device__ __forceinline__ void csr_gather_fp8(const uint8_t* hl, int node,
                                               float* acc) {
    unpack_e4m3_4(*(const uint32_t*)(hl + (size_t)node * FB), acc);
    int beg = g_rowptr[node], end = g_rowptr[node + 1];
    int j = beg;
    for (; j + 8 <= end; j += 8) {
        int sidx[8];
#pragma unroll
        for (int k = 0; k < 8; k++) sidx[k] = g_csrc[j + k];
        uint32_t v[8];
#pragma unroll
        for (int k = 0; k < 8; k++)
            v[k] = *(const uint32_t*)(hl + (size_t)sidx[k] * FB);
        uint32_t h01[8], h23[8];
#pragma unroll
        for (int k = 0; k < 8; k++) e4m3x4_to_h2(v[k], h01[k], h23[k]);
        __half2 a01 = __hadd2(__hadd2(*(__half2*)&h01[0], *(__half2*)&h01[1]),
                              __hadd2(*(__half2*)&h01[2], *(__half2*)&h01[3]));
        __half2 b01 = __hadd2(__hadd2(*(__half2*)&h01[4], *(__half2*)&h01[5]),
                              __hadd2(*(__half2*)&h01[6], *(__half2*)&h01[7]));
        __half2 a23 = __hadd2(__hadd2(*(__half2*)&h23[0], *(__half2*)&h23[1]),
                              __hadd2(*(__half2*)&h23[2], *(__half2*)&h23[3]));
        __half2 b23 = __hadd2(__hadd2(*(__half2*)&h23[4], *(__half2*)&h23[5]),
                              __hadd2(*(__half2*)&h23[6], *(__half2*)&h23[7]));
        __half2 s01 = __hadd2(a01, b01);
        __half2 s23 = __hadd2(a23, b23);
        float2 f01 = __half22float2(s01);
        float2 f23 = __half22float2(s23);
        acc[0] += f01.x; acc[1] += f01.y;
        acc[2] += f23.x; acc[3] += f23.y;
    }
    if (j + 4 <= end) {
        int s0 = g_csrc[j],     s1 = g_csrc[j + 1];
        int s2 = g_csrc[j + 2], s3 = g_csrc[j + 3];
        uint32_t v0 = *(const uint32_t*)(hl + (size_t)s0 * FB);
        uint32_t v1 = *(const uint32_t*)(hl + (size_t)s1 * FB);
        uint32_t v2 = *(const uint32_t*)(hl + (size_t)s2 * FB);
        uint32_t v3 = *(const uint32_t*)(hl + (size_t)s3 * FB);
        uint32_t a01, a23, b01, b23, c01, c23, d01, d23;
        e4m3x4_to_h2(v0, a01, a23);
        e4m3x4_to_h2(v1, b01, b23);
        e4m3x4_to_h2(v2, c01, c23);
        e4m3x4_to_h2(v3, d01, d23);
        __half2 s01 = __hadd2(__hadd2(*(__half2*)&a01, *(__half2*)&b01),
                              __hadd2(*(__half2*)&c01, *(__half2*)&d01));
        __half2 s23 = __hadd2(__hadd2(*(__half2*)&a23, *(__half2*)&b23),
                              __hadd2(*(__half2*)&c23, *(__half2*)&d23));
        float2 f01 = __half22float2(s01);
        float2 f23 = __half22float2(s23);
        acc[0] += f01.x; acc[1] += f01.y;
        acc[2] += f23.x; acc[3] += f23.y;
        j += 4;
    }
    for (; j < end; j++) {
        int s = g_csrc[j];
        float f[4];
        unpack_e4m3_4(*(const uint32_t*)(hl + (size_t)s * FB), f);
#pragma unroll
        for (int c = 0; c < 4; c++) acc[c] += f[c];
    }
}

// agg layer 1 (fp8 in/out): t1 = fp8(relu(dinv*gathersum + 16*b1))
// also re-zeroes g_degi for the next replay (degi is dead after scan23).
__global__ void __launch_bounds__(256)
k_agg1(const uint8_t* __restrict__ h, const float* __restrict__ b1,
       uint8_t* __restrict__ t1) {
    int gi = blockIdx.x * 256 + threadIdx.x;
    if (gi < NN) g_degi[gi] = 0;                 // prep next replay
    int node = gi >> 5;
    int lane = threadIdx.x & 31;
    if (node >= NN) return;
    float acc[4];
    csr_gather_fp8<128>(h + lane * 4, node, acc);
    float dn = g_dinv[node];
    float4 bb = *(const float4*)(b1 + lane * 4);
    float r0 = fmaxf(dn * acc[0] + 16.f * bb.x, 0.f);
    float r1 = fmaxf(dn * acc[1] + 16.f * bb.y, 0.f);
    float r2 = fmaxf(dn * acc[2] + 16.f * bb.z, 0.f);
    float r3 = fmaxf(dn * acc[3] + 16.f * bb.w, 0.f);
    uint16_t lo = pack_e4m3_2(r0, r1);
    uint16_t hi = pack_e4m3_2(r2, r3);
    *(uint32_t*)(t1 + (size_t)node * 128 + lane * 4) =
        (uint32_t)lo | ((uint32_t)hi << 16);
}

// agg layer 2 (fp8 input, 2 nodes/warp) + sigmoid + mean + output
__global__ void __launch_bounds__(256)
k_agg2(const uint8_t* __restrict__ h, const float* __restrict__ b2,
       float* __restrict__ out) {
    __shared__ float sm[64];
    if (threadIdx.x < 64) sm[threadIdx.x] = 0.f;
    __syncthreads();

    int lane = threadIdx.x & 31;
    int half = lane >> 4;
    int l16  = lane & 15;
    int wg   = (blockIdx.x * 256 + threadIdx.x) >> 5;
    int stride = gridDim.x * 8 * 2;

    float4 bb = *(const float4*)(b2 + l16 * 4);
    float s[4] = {0.f, 0.f, 0.f, 0.f};

    for (int node = wg * 2 + half; node < NN; node += stride) {
        float acc[4];
        csr_gather_fp8<64>(h + l16 * 4, node, acc);
        float dn = g_dinv[node] * 0.0625f;       // undo x16 fp8 scale
        s[0] += 1.0f / (1.0f + __expf(-(dn * acc[0] + bb.x)));
        s[1] += 1.0f / (1.0f + __expf(-(dn * acc[1] + bb.y)));
        s[2] += 1.0f / (1.0f + __expf(-(dn * acc[2] + bb.z)));
        s[3] += 1.0f / (1.0f + __expf(-(dn * acc[3] + bb.w)));
    }
#pragma unroll
    for (int c = 0; c < 4; c++) atomicAdd(&sm[l16 * 4 + c], s[c]);
    __syncthreads();
    if (threadIdx.x < 64) atomicAdd(&g_acc[threadIdx.x], sm[threadIdx.x]);
    __threadfence();
    __syncthreads();

    __shared__ unsigned s_last;
    if (threadIdx.x == 0)
        s_last = (atomicAdd(&g_done, 1u) == (unsigned)(gridDim.x - 1));
    __syncthreads();
    if (s_last) {
        __threadfence();
        if (threadIdx.x < 64) {
            float v = atomicAdd(&g_acc[threadIdx.x], 0.f);
            out[threadIdx.x] = v * (1.0f / NN);
        }
    }
}

// ---------------- launch ----------------
extern "C" void kernel_launch(void* const* d_in, const int* in_sizes, int n_in,
                              void* d_out, int out_size) {
    const float* x  = (const float*)d_in[0];
    const void*  ei = d_in[1];
    const float* W1 = (const float*)d_in[2];
    const float* b1 = (const float*)d_in[3];
    const float* W2 = (const float*)d_in[4];
    const float* b2 = (const float*)d_in[5];
    float* out = (float*)d_out;
    long long E = in_sizes[1] / 2;

    uint8_t *h1, *t1, *h2;
    float *dinv;
    cudaGetSymbolAddress((void**)&h1, g_h1);
    cudaGetSymbolAddress((void**)&t1, g_t1);
    cudaGetSymbolAddress((void**)&h2, g_h2);
    cudaGetSymbolAddress((void**)&dinv, g_dinv);

    const int SM1 = (128 * 136 + 128 * 136) * 2;  // 69632 B
    const int SM2 = (128 * 136 + 128 * 72) * 2;   // 53248 B

    static cudaStream_t s2 = nullptr;
    static cudaEvent_t ev0 = nullptr, ev1 = nullptr;
    if (!s2) {
        cudaFuncSetAttribute(k_gemm_tc<128, 0>,
                             cudaFuncAttributeMaxDynamicSharedMemorySize, SM1);
        cudaFuncSetAttribute(k_gemm_tc<64, 2>,
                             cudaFuncAttributeMaxDynamicSharedMemorySize, SM2);
        cudaStreamCreateWithFlags(&s2, cudaStreamNonBlocking);
        cudaEventCreateWithFlags(&ev0, cudaEventDisableTiming);
        cudaEventCreateWithFlags(&ev1, cudaEventDisableTiming);
    }

    int eb4 = (int)((E + 1023) / 1024);   // 4 edges per thread
    int gb = (NN + 127) / 128;
    int wb = (NN * 32 + 255) / 256;

    // preprocessing chain (main stream) — degi zeroed by previous call's k_agg1
    k_degcount<<<eb4, 256>>>(ei, E);
    k_scan1<<<NB, 256>>>();

    // fork: GEMM1 on side stream (needs dinv from scan1)
    cudaEventRecord(ev1, 0);
    cudaStreamWaitEvent(s2, ev1, 0);
    k_gemm_tc<128, 0><<<gb, 256, SM1, s2>>>(x, W1, dinv, 16.f, h1, NN);
    cudaEventRecord(ev0, s2);

    k_scan23<<<NB, 256>>>();
    k_scatter<<<eb4, 256>>>(ei, E);

    // join: agg1 needs CSR (main) + h1 (s2)
    cudaStreamWaitEvent(0, ev0, 0);
    k_agg1<<<wb, 256>>>(h1, b1, t1);

    // Layer 2
    k_gemm_tc<64, 2><<<gb, 256, SM2>>>(t1, W2, dinv, 1.f, h2, NN);
    k_agg2<<<1480, 256>>>(h2, b2, out);
}

// round 16
// speedup vs baseline: 1.0214x; 1.0214x over previous
#include <cuda_runtime.h>
#include <cuda_bf16.h>
#include <cuda_fp16.h>
#include <cstdint>
#include <cstddef>

#define NN   100000
#define MAXE 1600000
#define NB   391          // ceil(NN/256)

// ---------------- device scratch ----------------
__device__ int   g_degi[NN];       // zero at process start; re-zeroed by k_agg1
__device__ float g_dinv[NN];
__device__ int   g_rowptr[NN + 1];
__device__ int   g_bsum[NB];
__device__ int   g_epos[MAXE];     // within-bucket rank of each edge
__device__ int   g_csrc[MAXE];
__device__ uint8_t g_h1[(size_t)NN * 128];  // fp8: 16*dinv*(x@W1)
__device__ uint8_t g_t1[(size_t)NN * 128];  // fp8: 16*relu(agg1+b1)
__device__ uint8_t g_h2[(size_t)NN * 64];   // fp8: 16*dinv*(t1@W2)
__device__ float g_acc[64];
__device__ unsigned int g_done;

// ---------------- inline edge dtype detection (per block) -----------------
__device__ __forceinline__ int detect_e64(const void* eidx, int* sh) {
    if (threadIdx.x < 32) {
        unsigned long long v = ((const unsigned long long*)eidx)[threadIdx.x];
        unsigned m = __ballot_sync(0xffffffffu, (v >> 32) != 0ULL);
        if (threadIdx.x == 0) *sh = (m == 0u);
    }
    __syncthreads();
    return *sh;
}

// ---------------- degree count (4 edges/thread, records bucket rank) ------
__global__ void k_degcount(const void* __restrict__ eidx, long long E) {
    __shared__ int sh;
    int e64 = detect_e64(eidx, &sh);
    long long base = (blockIdx.x * (long long)blockDim.x + threadIdx.x) * 4;
    if (base >= E) return;
    bool fast = (base + 3 < E) && ((E & 3LL) == 0);
    if (e64) {
        const long long* p = (const long long*)eidx + E;   // dst half
        if (fast) {
            longlong4 d4 = *(const longlong4*)(p + base);
            int4 r;
            r.x = atomicAdd(&g_degi[(int)d4.x], 1);
            r.y = atomicAdd(&g_degi[(int)d4.y], 1);
            r.z = atomicAdd(&g_degi[(int)d4.z], 1);
            r.w = atomicAdd(&g_degi[(int)d4.w], 1);
            *(int4*)&g_epos[base] = r;
        } else {
            for (int k = 0; k < 4 && base + k < E; k++)
                g_epos[base + k] = atomicAdd(&g_degi[(int)p[base + k]], 1);
        }
    } else {
        const int* p = (const int*)eidx + E;
        if (fast) {
            int4 d4 = *(const int4*)(p + base);
            int4 r;
            r.x = atomicAdd(&g_degi[d4.x], 1);
            r.y = atomicAdd(&g_degi[d4.y], 1);
            r.z = atomicAdd(&g_degi[d4.z], 1);
            r.w = atomicAdd(&g_degi[d4.w], 1);
            *(int4*)&g_epos[base] = r;
        } else {
            for (int k = 0; k < 4 && base + k < E; k++)
                g_epos[base + k] = atomicAdd(&g_degi[p[base + k]], 1);
        }
    }
}

// ---------------- scan stage 1: per-tile totals (+ dinv), shuffle ---------
__global__ void k_scan1() {
    __shared__ int ws[8];
    int i = blockIdx.x * 256 + threadIdx.x;
    int v = (i < NN) ? g_degi[i] : 0;
    if (i < NN) g_dinv[i] = rsqrtf((float)(v + 1));   // +1 self loop
    int t = v;
#pragma unroll
    for (int o = 16; o > 0; o >>= 1) t += __shfl_down_sync(0xffffffffu, t, o);
    if ((threadIdx.x & 31) == 0) ws[threadIdx.x >> 5] = t;
    __syncthreads();
    if (threadIdx.x == 0) {
        int s = 0;
#pragma unroll
        for (int k = 0; k < 8; k++) s += ws[k];
        g_bsum[blockIdx.x] = s;
    }
}

// -------- scan stage 2+3 merged: rowptr (+ zero acc/done), shuffle --------
__global__ void k_scan23() {
    __shared__ int ws[8];     // per-warp partial sums of bsum[0..bid)
    __shared__ int wtot[8];   // per-warp totals of local inclusive scan
    int bid  = blockIdx.x;
    int lane = threadIdx.x & 31;
    int w    = threadIdx.x >> 5;

    // block offset = sum of bsum[0..bid)
    int partial = 0;
    for (int j = threadIdx.x; j < bid; j += 256) partial += g_bsum[j];
    int t = partial;
#pragma unroll
    for (int o = 16; o > 0; o >>= 1) t += __shfl_down_sync(0xffffffffu, t, o);
    if (lane == 0) ws[w] = t;

    // local inclusive scan of this tile's degrees (warp shfl scan)
    int i = bid * 256 + threadIdx.x;
    int v = (i < NN) ? g_degi[i] : 0;
    int incl = v;
#pragma unroll
    for (int o = 1; o < 32; o <<= 1) {
        int y = __shfl_up_sync(0xffffffffu, incl, o);
        if (lane >= o) incl += y;
    }
    if (lane == 31) wtot[w] = incl;
    __syncthreads();

    int boff = 0;
#pragma unroll
    for (int k = 0; k < 8; k++) boff += ws[k];
    int woff = 0;
    for (int k = 0; k < w; k++) woff += wtot[k];

    int excl = boff + woff + incl - v;
    if (i < NN) g_rowptr[i] = excl;
    if (i == NN - 1) g_rowptr[NN] = excl + v;

    if (bid == 0) {
        if (threadIdx.x < 64) g_acc[threadIdx.x] = 0.f;
        if (threadIdx.x == 64) g_done = 0u;
    }
}

// ---------------- scatter: atomic-free, 4 edges/thread --------------------
__global__ void k_scatter(const void* __restrict__ eidx, long long E) {
    __shared__ int sh;
    int e64 = detect_e64(eidx, &sh);
    long long base = (blockIdx.x * (long long)blockDim.x + threadIdx.x) * 4;
    if (base >= E) return;
    bool fast = (base + 3 < E) && ((E & 3LL) == 0);
    if (e64) {
        const long long* ps = (const long long*)eidx;
        const long long* pd = ps + E;
        if (fast) {
            longlong4 s4 = *(const longlong4*)(ps + base);
            longlong4 d4 = *(const longlong4*)(pd + base);
            int4 ep = *(const int4*)&g_epos[base];
            g_csrc[g_rowptr[(int)d4.x] + ep.x] = (int)s4.x;
            g_csrc[g_rowptr[(int)d4.y] + ep.y] = (int)s4.y;
            g_csrc[g_rowptr[(int)d4.z] + ep.z] = (int)s4.z;
            g_csrc[g_rowptr[(int)d4.w] + ep.w] = (int)s4.w;
        } else {
            for (int k = 0; k < 4 && base + k < E; k++)
                g_csrc[g_rowptr[(int)pd[base + k]] + g_epos[base + k]] =
                    (int)ps[base + k];
        }
    } else {
        const int* ps = (const int*)eidx;
        const int* pd = ps + E;
        if (fast) {
            int4 s4 = *(const int4*)(ps + base);
            int4 d4 = *(const int4*)(pd + base);
            int4 ep = *(const int4*)&g_epos[base];
            g_csrc[g_rowptr[d4.x] + ep.x] = s4.x;
            g_csrc[g_rowptr[d4.y] + ep.y] = s4.y;
            g_csrc[g_rowptr[d4.z] + ep.z] = s4.z;
            g_csrc[g_rowptr[d4.w] + ep.w] = s4.w;
        } else {
            for (int k = 0; k < 4 && base + k < E; k++)
                g_csrc[g_rowptr[pd[base + k]] + g_epos[base + k]] = ps[base + k];
        }
    }
}

// ---------------- fp8 helpers ----------------
__device__ __forceinline__ uint16_t pack_e4m3_2(float lo, float hi) {
    uint16_t r;
    asm("cvt.rn.satfinite.e4m3x2.f32 %0, %1, %2;" : "=h"(r) : "f"(hi), "f"(lo));
    return r;
}
__device__ __forceinline__ void e4m3x4_to_h2(uint32_t v, uint32_t& h01, uint32_t& h23) {
    asm("cvt.rn.f16x2.e4m3x2 %0, %1;" : "=r"(h01)
        : "h"((unsigned short)(v & 0xffffu)));
    asm("cvt.rn.f16x2.e4m3x2 %0, %1;" : "=r"(h23)
        : "h"((unsigned short)(v >> 16)));
}
__device__ __forceinline__ void unpack_e4m3_4(uint32_t v, float* f) {
    uint32_t h01, h23;
    e4m3x4_to_h2(v, h01, h23);
    float2 fa = __half22float2(*reinterpret_cast<__half2*>(&h01));
    float2 fb = __half22float2(*reinterpret_cast<__half2*>(&h23));
    f[0] = fa.x; f[1] = fa.y; f[2] = fb.x; f[3] = fb.y;
}
__device__ __forceinline__ uint2 fp8x4_to_bf16x4(uint32_t v) {
    float f[4];
    unpack_e4m3_4(v, f);
    __nv_bfloat162 lo = __float22bfloat162_rn(make_float2(f[0], f[1]));
    __nv_bfloat162 hi = __float22bfloat162_rn(make_float2(f[2], f[3]));
    return make_uint2(*(uint32_t*)&lo, *(uint32_t*)&hi);
}

// ---------------- tensor-core GEMM primitives ----------------
__device__ __forceinline__ uint32_t smem_u32(const void* p) {
    return (uint32_t)__cvta_generic_to_shared(p);
}
__device__ __forceinline__ void ldsm4(uint32_t* r, uint32_t addr) {
    asm volatile("ldmatrix.sync.aligned.m8n8.x4.shared.b16 {%0,%1,%2,%3},[%4];"
                 : "=r"(r[0]), "=r"(r[1]), "=r"(r[2]), "=r"(r[3]) : "r"(addr));
}
__device__ __forceinline__ void ldsm4t(uint32_t* r, uint32_t addr) {
    asm volatile("ldmatrix.sync.aligned.m8n8.x4.trans.shared.b16 {%0,%1,%2,%3},[%4];"
                 : "=r"(r[0]), "=r"(r[1]), "=r"(r[2]), "=r"(r[3]) : "r"(addr));
}
__device__ __forceinline__ void mma16816(float* d, const uint32_t* a, const uint32_t* b) {
    asm volatile(
        "mma.sync.aligned.m16n8k16.row.col.f32.bf16.bf16.f32 "
        "{%0,%1,%2,%3},{%4,%5,%6,%7},{%8,%9},{%0,%1,%2,%3};"
        : "+f"(d[0]), "+f"(d[1]), "+f"(d[2]), "+f"(d[3])
        : "r"(a[0]), "r"(a[1]), "r"(a[2]), "r"(a[3]), "r"(b[0]), "r"(b[1]));
}

// C[nrows,BN](fp8) = osc * rowscale[r] * (A[nrows,128] @ W[128,BN]).
// AMODE: 0 = A is fp32, 2 = A is fp8 (unpacked exactly to bf16).
template <int BN, int AMODE>
__global__ void __launch_bounds__(256)
k_gemm_tc(const void* __restrict__ Av, const float* __restrict__ W,
          const float* __restrict__ rowscale, float osc,
          uint8_t* __restrict__ C, int nrows) {
    const int LDA = 136;
    const int LDB = BN + 8;
    extern __shared__ __nv_bfloat16 smem[];
    __nv_bfloat16* As = smem;
    __nv_bfloat16* Bs = smem + 128 * LDA;

    int tid  = threadIdx.x;
    int lane = tid & 31;
    int w    = tid >> 5;
    int wm   = w & 3;
    int wn   = w >> 2;
    int row0 = blockIdx.x * 128;

    if (AMODE == 2) {
        const uint8_t* A = (const uint8_t*)Av;
        for (int idx = tid; idx < 128 * 16; idx += 256) {
            int r = idx >> 4, c8 = (idx & 15) * 8;
            uint2 v = make_uint2(0u, 0u);
            if (row0 + r < nrows)
                v = *(const uint2*)(A + (size_t)(row0 + r) * 128 + c8);
            uint2 lo = fp8x4_to_bf16x4(v.x);
            uint2 hi = fp8x4_to_bf16x4(v.y);
            *(uint4*)&As[r * LDA + c8] = make_uint4(lo.x, lo.y, hi.x, hi.y);
        }
    } else {
        const float* A = (const float*)Av;
        for (int idx = tid; idx < 128 * 32; idx += 256) {
            int r = idx >> 5, c4 = (idx & 31) * 4;
            float4 v = make_float4(0.f, 0.f, 0.f, 0.f);
            if (row0 + r < nrows)
                v = *(const float4*)(A + (size_t)(row0 + r) * 128 + c4);
            __nv_bfloat162 lo = __float22bfloat162_rn(make_float2(v.x, v.y));
            __nv_bfloat162 hi = __float22bfloat162_rn(make_float2(v.z, v.w));
            uint2 pk;
            pk.x = *(uint32_t*)&lo;
            pk.y = *(uint32_t*)&hi;
            *(uint2*)&As[r * LDA + c4] = pk;
        }
    }
    for (int idx = tid; idx < 128 * (BN / 4); idx += 256) {
        int r = idx / (BN / 4), c4 = (idx % (BN / 4)) * 4;
        float4 v = *(const float4*)(W + (size_t)r * BN + c4);
        __nv_bfloat162 lo = __float22bfloat162_rn(make_float2(v.x, v.y));
        __nv_bfloat162 hi = __float22bfloat162_rn(make_float2(v.z, v.w));
        uint2 pk;
        pk.x = *(uint32_t*)&lo;
        pk.y = *(uint32_t*)&hi;
        *(uint2*)&Bs[r * LDB + c4] = pk;
    }
    __syncthreads();

    const int NF8 = BN / 16;
    const int NT  = NF8 / 2;
    float acc[2][NF8][4];
#pragma unroll
    for (int i = 0; i < 2; i++)
#pragma unroll
        for (int j = 0; j < NF8; j++)
#pragma unroll
            for (int q = 0; q < 4; q++) acc[i][j][q] = 0.f;

    int rsel = lane & 15;
    int csel = (lane >> 4) * 8;
    int mw0  = wm * 32;
    int nw0  = wn * (BN / 2);

#pragma unroll
    for (int ks = 0; ks < 8; ks++) {
        int k0 = ks * 16;
        uint32_t af[2][4];
#pragma unroll
        for (int mi = 0; mi < 2; mi++)
            ldsm4(af[mi], smem_u32(&As[(mw0 + mi * 16 + rsel) * LDA + k0 + csel]));
        uint32_t bf[NT][4];
#pragma unroll
        for (int nt = 0; nt < NT; nt++)
            ldsm4t(bf[nt], smem_u32(&Bs[(k0 + rsel) * LDB + nw0 + nt * 16 + csel]));
#pragma unroll
        for (int mi = 0; mi < 2; mi++)
#pragma unroll
            for (int nj = 0; nj < NF8; nj++)
                mma16816(acc[mi][nj], af[mi], &bf[nj >> 1][(nj & 1) * 2]);
    }

    int g = lane >> 2, q = lane & 3;
#pragma unroll
    for (int mi = 0; mi < 2; mi++) {
        int r0 = row0 + mw0 + mi * 16 + g;
        float sc0 = (r0 < nrows)     ? rowscale[r0] * osc     : 0.f;
        float sc1 = (r0 + 8 < nrows) ? rowscale[r0 + 8] * osc : 0.f;
#pragma unroll
        for (int nj = 0; nj < NF8; nj++) {
            int col = nw0 + nj * 8 + q * 2;
            if (r0 < nrows)
                *(uint16_t*)(C + (size_t)r0 * BN + col) =
                    pack_e4m3_2(acc[mi][nj][0] * sc0, acc[mi][nj][1] * sc0);
            if (r0 + 8 < nrows)
                *(uint16_t*)(C + (size_t)(r0 + 8) * BN + col) =
                    pack_e4m3_2(acc[mi][nj][2] * sc1, acc[mi][nj][3] * sc1);
        }
    }
}

// ------- CSR fp8 gather-sum, half2 inner tree + fp32 outer accumulator ----
template <int FB>
__device__ __forceinline__ void csr_gather_fp8(const uint8_t* hl, int node,
                                               float* acc) {
    unpack_e4m3_4(*(const uint32_t*)(hl + (size_t)node * FB), acc);
    int beg = g_rowptr[node], end = g_rowptr[node + 1];
    int j = beg;
    for (; j + 4 <= end; j += 4) {
        int s0 = g_csrc[j],     s1 = g_csrc[j + 1];
        int s2 = g_csrc[j + 2], s3 = g_csrc[j + 3];
        uint32_t v0 = *(const uint32_t*)(hl + (size_t)s0 * FB);
        uint32_t v1 = *(const uint32_t*)(hl + (size_t)s1 * FB);
        uint32_t v2 = *(const uint32_t*)(hl + (size_t)s2 * FB);
        uint32_t v3 = *(const uint32_t*)(hl + (size_t)s3 * FB);
        uint32_t a01, a23, b01, b23, c01, c23, d01, d23;
        e4m3x4_to_h2(v0, a01, a23);
        e4m3x4_to_h2(v1, b01, b23);
        e4m3x4_to_h2(v2, c01, c23);
        e4m3x4_to_h2(v3, d01, d23);
        __half2 s01 = __hadd2(__hadd2(*(__half2*)&a01, *(__half2*)&b01),
                              __hadd2(*(__half2*)&c01, *(__half2*)&d01));
        __half2 s23 = __hadd2(__hadd2(*(__half2*)&a23, *(__half2*)&b23),
                              __hadd2(*(__half2*)&c23, *(__half2*)&d23));
        float2 f01 = __half22float2(s01);
        float2 f23 = __half22float2(s23);
        acc[0] += f01.x; acc[1] += f01.y;
        acc[2] += f23.x; acc[3] += f23.y;
    }
    for (; j < end; j++) {
        int s = g_csrc[j];
        float f[4];
        unpack_e4m3_4(*(const uint32_t*)(hl + (size_t)s * FB), f);
#pragma unroll
        for (int c = 0; c < 4; c++) acc[c] += f[c];
    }
}

// agg layer 1 (fp8 in/out): t1 = fp8(relu(dinv*gathersum + 16*b1))
// also re-zeroes g_degi for the next replay (degi is dead after scan23).
__global__ void __launch_bounds__(256)
k_agg1(const uint8_t* __restrict__ h, const float* __restrict__ b1,
       uint8_t* __restrict__ t1) {
    int gi = blockIdx.x * 256 + threadIdx.x;
    if (gi < NN) g_degi[gi] = 0;                 // prep next replay
    int node = gi >> 5;
    int lane = threadIdx.x & 31;
    if (node >= NN) return;
    float acc[4];
    csr_gather_fp8<128>(h + lane * 4, node, acc);
    float dn = g_dinv[node];
    float4 bb = *(const float4*)(b1 + lane * 4);
    float r0 = fmaxf(dn * acc[0] + 16.f * bb.x, 0.f);
    float r1 = fmaxf(dn * acc[1] + 16.f * bb.y, 0.f);
    float r2 = fmaxf(dn * acc[2] + 16.f * bb.z, 0.f);
    float r3 = fmaxf(dn * acc[3] + 16.f * bb.w, 0.f);
    uint16_t lo = pack_e4m3_2(r0, r1);
    uint16_t hi = pack_e4m3_2(r2, r3);
    *(uint32_t*)(t1 + (size_t)node * 128 + lane * 4) =
        (uint32_t)lo | ((uint32_t)hi << 16);
}

// agg layer 2 (fp8 input, 2 nodes/warp) + sigmoid + mean + output
__global__ void __launch_bounds__(256)
k_agg2(const uint8_t* __restrict__ h, const float* __restrict__ b2,
       float* __restrict__ out) {
    __shared__ float sm[64];
    if (threadIdx.x < 64) sm[threadIdx.x] = 0.f;
    __syncthreads();

    int lane = threadIdx.x & 31;
    int half = lane >> 4;
    int l16  = lane & 15;
    int wg   = (blockIdx.x * 256 + threadIdx.x) >> 5;
    int stride = gridDim.x * 8 * 2;

    float4 bb = *(const float4*)(b2 + l16 * 4);
    float s[4] = {0.f, 0.f, 0.f, 0.f};

    for (int node = wg * 2 + half; node < NN; node += stride) {
        float acc[4];
        csr_gather_fp8<64>(h + l16 * 4, node, acc);
        float dn = g_dinv[node] * 0.0625f;       // undo x16 fp8 scale
        s[0] += 1.0f / (1.0f + __expf(-(dn * acc[0] + bb.x)));
        s[1] += 1.0f / (1.0f + __expf(-(dn * acc[1] + bb.y)));
        s[2] += 1.0f / (1.0f + __expf(-(dn * acc[2] + bb.z)));
        s[3] += 1.0f / (1.0f + __expf(-(dn * acc[3] + bb.w)));
    }
#pragma unroll
    for (int c = 0; c < 4; c++) atomicAdd(&sm[l16 * 4 + c], s[c]);
    __syncthreads();
    if (threadIdx.x < 64) atomicAdd(&g_acc[threadIdx.x], sm[threadIdx.x]);
    __threadfence();
    __syncthreads();

    __shared__ unsigned s_last;
    if (threadIdx.x == 0)
        s_last = (atomicAdd(&g_done, 1u) == (unsigned)(gridDim.x - 1));
    __syncthreads();
    if (s_last) {
        __threadfence();
        if (threadIdx.x < 64) {
            float v = atomicAdd(&g_acc[threadIdx.x], 0.f);
            out[threadIdx.x] = v * (1.0f / NN);
        }
    }
}

// ---------------- launch ----------------
extern "C" void kernel_launch(void* const* d_in, const int* in_sizes, int n_in,
                              void* d_out, int out_size) {
    const float* x  = (const float*)d_in[0];
    const void*  ei = d_in[1];
    const float* W1 = (const float*)d_in[2];
    const float* b1 = (const float*)d_in[3];
    const float* W2 = (const float*)d_in[4];
    const float* b2 = (const float*)d_in[5];
    float* out = (float*)d_out;
    long long E = in_sizes[1] / 2;

    uint8_t *h1, *t1, *h2;
    float *dinv;
    cudaGetSymbolAddress((void**)&h1, g_h1);
    cudaGetSymbolAddress((void**)&t1, g_t1);
    cudaGetSymbolAddress((void**)&h2, g_h2);
    cudaGetSymbolAddress((void**)&dinv, g_dinv);

    const int SM1 = (128 * 136 + 128 * 136) * 2;  // 69632 B
    const int SM2 = (128 * 136 + 128 * 72) * 2;   // 53248 B

    static cudaStream_t s2 = nullptr;
    static cudaEvent_t ev0 = nullptr, ev1 = nullptr;
    if (!s2) {
        cudaFuncSetAttribute(k_gemm_tc<128, 0>,
                             cudaFuncAttributeMaxDynamicSharedMemorySize, SM1);
        cudaFuncSetAttribute(k_gemm_tc<64, 2>,
                             cudaFuncAttributeMaxDynamicSharedMemorySize, SM2);
        cudaStreamCreateWithFlags(&s2, cudaStreamNonBlocking);
        cudaEventCreateWithFlags(&ev0, cudaEventDisableTiming);
        cudaEventCreateWithFlags(&ev1, cudaEventDisableTiming);
    }

    int eb4 = (int)((E + 1023) / 1024);   // 4 edges per thread
    int gb = (NN + 127) / 128;
    int wb = (NN * 32 + 255) / 256;

    // preprocessing chain (main stream) — degi zeroed by previous call's k_agg1
    k_degcount<<<eb4, 256>>>(ei, E);
    k_scan1<<<NB, 256>>>();

    // fork: GEMM1 on side stream (needs dinv from scan1)
    cudaEventRecord(ev1, 0);
    cudaStreamWaitEvent(s2, ev1, 0);
    k_gemm_tc<128, 0><<<gb, 256, SM1, s2>>>(x, W1, dinv, 16.f, h1, NN);
    cudaEventRecord(ev0, s2);

    k_scan23<<<NB, 256>>>();
    k_scatter<<<eb4, 256>>>(ei, E);

    // join: agg1 needs CSR (main) + h1 (s2)
    cudaStreamWaitEvent(0, ev0, 0);
    k_agg1<<<wb, 256>>>(h1, b1, t1);

    // Layer 2
    k_gemm_tc<64, 2><<<gb, 256, SM2>>>(t1, W2, dinv, 1.f, h2, NN);
    k_agg2<<<1184, 256>>>(h2, b2, out);
}